// round 6
// baseline (speedup 1.0000x reference)
#include <cuda_runtime.h>
#include <cuda_bf16.h>
#include <cstdint>

// ---------------- problem constants ----------------
#define BATCH    16
#define ZDIM     512
#define TSEQ     4096
#define NGROUPS  2
#define NENTRIES 320
#define VDIM     128
#define MROWS    (BATCH * TSEQ)          // 65536
#define NCOLS    (NGROUPS * NENTRIES)    // 640
#define KDIM     ZDIM                    // 512
#define LOGITS_ELEMS ((size_t)MROWS * NCOLS)

// ---------------- GEMM tiling ----------------
#define M_TILE   128
#define N_TILE   128
#define KC       64                      // k per chunk
#define NCHUNK   (KDIM / KC)             // 8
#define THREADS  256
#define NHALVES  10

// SMEM: A double buffer (k-major, hi+lo) + B 4-stage ring (hi+lo)
#define A_COMP     16384                 // 64 k-rows x 256B
#define A_SLOT     (2 * A_COMP)          // 32 KB
#define OFF_B      (2 * A_SLOT)          // 64 KB
#define B_COMP     16384                 // 128 n-rows x 128B
#define BSTAGE     (2 * B_COMP)          // 32 KB
#define SMEM_BYTES (OFF_B + 4 * BSTAGE)  // 192 KB

// ---------------- device scratch ----------------
__device__ __nv_bfloat16 g_whi[NCOLS * KDIM];
__device__ __nv_bfloat16 g_wlo[NCOLS * KDIM];
__device__ float2 g_part[(size_t)NHALVES * MROWS];

__device__ __forceinline__ uint32_t smem_u32(const void* p) {
    uint32_t a;
    asm("{ .reg .u64 t; cvta.to.shared.u64 t, %1; cvt.u32.u64 %0, t; }" : "=r"(a) : "l"(p));
    return a;
}

#define CP_ASYNC16(dst, src) \
    asm volatile("cp.async.cg.shared.global [%0], [%1], 16;" :: "r"(dst), "l"(src))
#define CP_COMMIT() asm volatile("cp.async.commit_group;")
#define CP_WAIT2()  asm volatile("cp.async.wait_group 2;")

__device__ __forceinline__ void ldm_x4(uint32_t addr, uint32_t& r0, uint32_t& r1,
                                       uint32_t& r2, uint32_t& r3) {
    asm volatile("ldmatrix.sync.aligned.m8n8.x4.shared.b16 {%0,%1,%2,%3}, [%4];"
                 : "=r"(r0), "=r"(r1), "=r"(r2), "=r"(r3) : "r"(addr));
}
__device__ __forceinline__ void ldm_x4t(uint32_t addr, uint32_t& r0, uint32_t& r1,
                                        uint32_t& r2, uint32_t& r3) {
    asm volatile("ldmatrix.sync.aligned.m8n8.x4.trans.shared.b16 {%0,%1,%2,%3}, [%4];"
                 : "=r"(r0), "=r"(r1), "=r"(r2), "=r"(r3) : "r"(addr));
}

__device__ __forceinline__ void mma_bf16(float& c0, float& c1, float& c2, float& c3,
                                         uint32_t a0, uint32_t a1, uint32_t a2, uint32_t a3,
                                         uint32_t b0, uint32_t b1) {
    asm volatile("mma.sync.aligned.m16n8k16.row.col.f32.bf16.bf16.f32 "
                 "{%0,%1,%2,%3}, {%4,%5,%6,%7}, {%8,%9}, {%0,%1,%2,%3};"
                 : "+f"(c0), "+f"(c1), "+f"(c2), "+f"(c3)
                 : "r"(a0), "r"(a1), "r"(a2), "r"(a3), "r"(b0), "r"(b1));
}

// B smem: 128B rows (64 k bf16), unit16 swizzled by row&7
__device__ __forceinline__ uint32_t sw_b(int row, int c16) {
    return (uint32_t)(row * 128 + ((c16 ^ (row & 7)) << 4));
}
// A smem: k-major 256B rows (128 m bf16), unit16 swizzled by krow&7
__device__ __forceinline__ uint32_t sw_a(int krow, int munit) {
    return (uint32_t)(krow * 256 + ((munit ^ (krow & 7)) << 4));
}

// ============================================================
// Pre-pass: split proj_w fp32 -> bf16 hi/lo
// ============================================================
__global__ __launch_bounds__(1024)
void split_w_kernel(const float* __restrict__ w) {
    int idx = blockIdx.x * blockDim.x + threadIdx.x;
    if (idx < NCOLS * KDIM) {
        float v = w[idx];
        __nv_bfloat16 hi = __float2bfloat16(v);
        g_whi[idx] = hi;
        g_wlo[idx] = __float2bfloat16(v - __bfloat162float(hi));
    }
}

// ============================================================
// GEMM + fused logits write + perturbed partial argmax.
// grid (5, 512), 256 threads, 1 CTA/SM, 192 KB smem.
// ============================================================
__global__ __launch_bounds__(THREADS, 1)
void pq_gemm_kernel(const float* __restrict__ x,      // (B, Z, T)
                    const float* __restrict__ bias,
                    const float* __restrict__ gumbel,  // (BT, 640)
                    float* __restrict__ logits)
{
    extern __shared__ char smem[];
    const uint32_t sbase = smem_u32(smem);
    const int tid  = threadIdx.x;
    const int wid  = tid >> 5;
    const int lane = tid & 31;
    const int m0   = blockIdx.y * M_TILE;
    const int n0   = blockIdx.x * N_TILE;
    const int b    = m0 >> 12;
    const int t0   = m0 & 4095;

    const int mwarp = wid >> 1;
    const int nwarp = wid & 1;

    float acc[2][8][4];
#pragma unroll
    for (int mi = 0; mi < 2; mi++)
#pragma unroll
        for (int nf = 0; nf < 8; nf++)
#pragma unroll
            for (int r = 0; r < 4; r++) acc[mi][nf][r] = 0.0f;

    // A direct-load: warp owns k-rows wid*8..wid*8+7; lane covers 4 t
    const float* xrow0 = x + ((size_t)b * KDIM + (size_t)(wid * 8)) * TSEQ + t0 + lane * 4;
    float4 areg[8];

    // B cp.async mapping: row = tid>>1, 4 c16 units per thread per component
    const int lrow = tid >> 1;
    const int lcb  = (tid & 1) * 4;

    auto issue_b = [&](int c) {
        const int kk = c * KC;
        const uint32_t st = sbase + OFF_B + (uint32_t)(c & 3) * BSTAGE;
        const __nv_bfloat16* gh = g_whi + (size_t)(n0 + lrow) * KDIM + kk;
        const __nv_bfloat16* gl = g_wlo + (size_t)(n0 + lrow) * KDIM + kk;
#pragma unroll
        for (int u = 0; u < 4; u++) {
            int c16 = lcb + u;
            uint32_t so = sw_b(lrow, c16);
            CP_ASYNC16(st + so, gh + c16 * 8);
            CP_ASYNC16(st + B_COMP + so, gl + c16 * 8);
        }
        CP_COMMIT();
    };

    auto lda = [&](int c) {
#pragma unroll
        for (int i = 0; i < 8; i++)
            areg[i] = *(const float4*)(xrow0 + ((size_t)(c * KC) + i) * TSEQ);
    };

    lda(0);
    issue_b(0); issue_b(1); issue_b(2);

    for (int c = 0; c < NCHUNK; ++c) {
        // ---- convert A regs -> bf16 hi/lo smem ----
        {
            char* abuf = smem + (c & 1) * A_SLOT;
#pragma unroll
            for (int i = 0; i < 8; i++) {
                float4 v = areg[i];
                int k = wid * 8 + i;
                uint32_t off = (uint32_t)(k * 256) +
                               ((((uint32_t)(lane >> 1)) ^ (uint32_t)(k & 7)) << 4) +
                               (uint32_t)((lane & 1) * 8);
                __nv_bfloat16 h0 = __float2bfloat16(v.x);
                __nv_bfloat16 h1 = __float2bfloat16(v.y);
                __nv_bfloat16 h2 = __float2bfloat16(v.z);
                __nv_bfloat16 h3 = __float2bfloat16(v.w);
                __nv_bfloat162 hp0 = __halves2bfloat162(h0, h1);
                __nv_bfloat162 hp1 = __halves2bfloat162(h2, h3);
                ((uint2*)(abuf + off))[0] = make_uint2(*(uint32_t*)&hp0, *(uint32_t*)&hp1);
                __nv_bfloat162 lp0 = __halves2bfloat162(
                    __float2bfloat16(v.x - __bfloat162float(h0)),
                    __float2bfloat16(v.y - __bfloat162float(h1)));
                __nv_bfloat162 lp1 = __halves2bfloat162(
                    __float2bfloat16(v.z - __bfloat162float(h2)),
                    __float2bfloat16(v.w - __bfloat162float(h3)));
                ((uint2*)(abuf + A_COMP + off))[0] = make_uint2(*(uint32_t*)&lp0, *(uint32_t*)&lp1);
            }
        }
        if (c + 1 < NCHUNK) lda(c + 1);

        CP_WAIT2();
        __syncthreads();
        if (c + 3 < NCHUNK) issue_b(c + 3);
        else CP_COMMIT();

        const uint32_t abase = sbase + (uint32_t)(c & 1) * A_SLOT;
        const uint32_t bbase = sbase + OFF_B + (uint32_t)(c & 3) * BSTAGE;

        const int grp = lane >> 3;
        const int kq  = lane & 7;
        const int brow = nwarp * 64 + (lane & 7) + ((lane >> 4) << 3);

#pragma unroll
        for (int ks = 0; ks < 4; ks++) {
            const int arow = ks * 16 + ((grp >> 1) << 3) + kq;
            const int bc16 = ks * 2 + ((lane >> 3) & 1);

            uint32_t ah[2][4];
#pragma unroll
            for (int mi = 0; mi < 2; mi++) {
                int munit = ((mwarp * 32 + mi * 16) >> 3) + (grp & 1);
                ldm_x4t(abase + sw_a(arow, munit), ah[mi][0], ah[mi][1], ah[mi][2], ah[mi][3]);
            }
            uint32_t bh[4][4];
#pragma unroll
            for (int j = 0; j < 4; j++)
                ldm_x4(bbase + sw_b(brow + j * 16, bc16), bh[j][0], bh[j][1], bh[j][2], bh[j][3]);

            // P1: Ahi x Bhi
#pragma unroll
            for (int mi = 0; mi < 2; mi++)
#pragma unroll
                for (int nf = 0; nf < 8; nf++) {
                    int j = nf >> 1, h = (nf & 1) * 2;
                    mma_bf16(acc[mi][nf][0], acc[mi][nf][1], acc[mi][nf][2], acc[mi][nf][3],
                             ah[mi][0], ah[mi][1], ah[mi][2], ah[mi][3], bh[j][h], bh[j][h + 1]);
                }

            // P3: Alo x Bhi (retire bh after this)
            uint32_t al[2][4];
#pragma unroll
            for (int mi = 0; mi < 2; mi++) {
                int munit = ((mwarp * 32 + mi * 16) >> 3) + (grp & 1);
                ldm_x4t(abase + A_COMP + sw_a(arow, munit), al[mi][0], al[mi][1], al[mi][2], al[mi][3]);
            }
#pragma unroll
            for (int mi = 0; mi < 2; mi++)
#pragma unroll
                for (int nf = 0; nf < 8; nf++) {
                    int j = nf >> 1, h = (nf & 1) * 2;
                    mma_bf16(acc[mi][nf][0], acc[mi][nf][1], acc[mi][nf][2], acc[mi][nf][3],
                             al[mi][0], al[mi][1], al[mi][2], al[mi][3], bh[j][h], bh[j][h + 1]);
                }

            // P2: Ahi x Blo
            uint32_t bl[4][4];
#pragma unroll
            for (int j = 0; j < 4; j++)
                ldm_x4(bbase + B_COMP + sw_b(brow + j * 16, bc16), bl[j][0], bl[j][1], bl[j][2], bl[j][3]);
#pragma unroll
            for (int mi = 0; mi < 2; mi++)
#pragma unroll
                for (int nf = 0; nf < 8; nf++) {
                    int j = nf >> 1, h = (nf & 1) * 2;
                    mma_bf16(acc[mi][nf][0], acc[mi][nf][1], acc[mi][nf][2], acc[mi][nf][3],
                             ah[mi][0], ah[mi][1], ah[mi][2], ah[mi][3], bl[j][h], bl[j][h + 1]);
                }
        }
    }

    // ---- fused epilogue ----
    float bestv[4];
    int   besti[4];
#pragma unroll
    for (int rp = 0; rp < 4; rp++) { bestv[rp] = -3.4e38f; besti[rp] = 0; }

#pragma unroll
    for (int nf = 0; nf < 8; nf++) {
        int col = n0 + nwarp * 64 + nf * 8 + (lane & 3) * 2;
        float b0 = __ldg(bias + col);
        float b1 = __ldg(bias + col + 1);
#pragma unroll
        for (int mi = 0; mi < 2; mi++) {
            int row = m0 + mwarp * 32 + mi * 16 + (lane >> 2);
            float v00 = acc[mi][nf][0] + b0, v01 = acc[mi][nf][1] + b1;
            float v10 = acc[mi][nf][2] + b0, v11 = acc[mi][nf][3] + b1;
            *(float2*)(logits + (size_t)row * NCOLS + col)       = make_float2(v00, v01);
            *(float2*)(logits + (size_t)(row + 8) * NCOLS + col) = make_float2(v10, v11);
            float2 g0 = *(const float2*)(gumbel + (size_t)row * NCOLS + col);
            float2 g1 = *(const float2*)(gumbel + (size_t)(row + 8) * NCOLS + col);
            float p;
            int rp0 = mi * 2, rp1 = mi * 2 + 1;
            p = v00 + g0.x; if (p > bestv[rp0]) { bestv[rp0] = p; besti[rp0] = col; }
            p = v01 + g0.y; if (p > bestv[rp0]) { bestv[rp0] = p; besti[rp0] = col + 1; }
            p = v10 + g1.x; if (p > bestv[rp1]) { bestv[rp1] = p; besti[rp1] = col; }
            p = v11 + g1.y; if (p > bestv[rp1]) { bestv[rp1] = p; besti[rp1] = col + 1; }
        }
    }

#pragma unroll
    for (int rp = 0; rp < 4; rp++) {
#pragma unroll
        for (int off = 1; off <= 2; off <<= 1) {
            float ov = __shfl_xor_sync(0xffffffffu, bestv[rp], off);
            int   oi = __shfl_xor_sync(0xffffffffu, besti[rp], off);
            if (ov > bestv[rp] || (ov == bestv[rp] && oi < besti[rp])) {
                bestv[rp] = ov; besti[rp] = oi;
            }
        }
    }
    if ((lane & 3) == 0) {
        const int h = blockIdx.x * 2 + nwarp;
#pragma unroll
        for (int rp = 0; rp < 4; rp++) {
            int row = m0 + mwarp * 32 + (rp >> 1) * 16 + (rp & 1) * 8 + (lane >> 2);
            g_part[(size_t)h * MROWS + row] = make_float2(bestv[rp], __int_as_float(besti[rp]));
        }
    }
}

// ============================================================
// Combine: winner among 5 halves per group, gather codevector
// ============================================================
__global__ __launch_bounds__(256)
void pq_combine_kernel(const float* __restrict__ cv,
                       float* __restrict__ q)
{
    const int warp = (blockIdx.x * blockDim.x + threadIdx.x) >> 5;
    const int lane = threadIdx.x & 31;
    if (warp >= MROWS * NGROUPS) return;

    const int bt = warp >> 1;
    const int g  = warp & 1;

    float best = -3.4e38f;
    int   bcol = 0;
#pragma unroll
    for (int j = 0; j < 5; j++) {
        float2 p = g_part[(size_t)(g * 5 + j) * MROWS + bt];
        if (p.x > best) { best = p.x; bcol = __float_as_int(p.y); }
    }

    const float4* src = (const float4*)(cv + (size_t)bcol * VDIM);
    float4*       dst = (float4*)(q + (size_t)bt * (NGROUPS * VDIM) + g * VDIM);
    dst[lane] = src[lane];
}

// ============================================================
extern "C" void kernel_launch(void* const* d_in, const int* in_sizes, int n_in,
                              void* d_out, int out_size) {
    const float* x      = (const float*)d_in[0];
    const float* gumbel = (const float*)d_in[1];
    const float* proj_w = (const float*)d_in[2];
    const float* proj_b = (const float*)d_in[3];
    const float* cv     = (const float*)d_in[4];

    float* out    = (float*)d_out;
    float* logits = out;
    float* q      = out + LOGITS_ELEMS;

    split_w_kernel<<<(NCOLS * KDIM + 1023) / 1024, 1024>>>(proj_w);

    cudaFuncSetAttribute(pq_gemm_kernel,
                         cudaFuncAttributeMaxDynamicSharedMemorySize, SMEM_BYTES);
    pq_gemm_kernel<<<dim3(NCOLS / N_TILE, MROWS / M_TILE), THREADS, SMEM_BYTES>>>(
        x, proj_b, gumbel, logits);

    int blocks = (MROWS * NGROUPS * 32 + 255) / 256;
    pq_combine_kernel<<<blocks, 256>>>(cv, q);
}

// round 7
// speedup vs baseline: 1.0371x; 1.0371x over previous
#include <cuda_runtime.h>
#include <cuda_bf16.h>
#include <cstdint>

// ---------------- problem constants ----------------
#define BATCH    16
#define ZDIM     512
#define TSEQ     4096
#define NGROUPS  2
#define NENTRIES 320
#define VDIM     128
#define MROWS    (BATCH * TSEQ)          // 65536
#define NCOLS    (NGROUPS * NENTRIES)    // 640
#define KDIM     ZDIM                    // 512
#define LOGITS_ELEMS ((size_t)MROWS * NCOLS)

// ---------------- GEMM tiling (round-5 config) ----------------
#define M_TILE   128
#define N_TILE   128
#define KC       32
#define NCHUNK   (KDIM / KC)             // 16
#define THREADS  256
#define NHALVES  10

#define ABF_SLOT   16384
#define OFF_ABF    0
#define OFF_B      32768
#define BSTAGE     16384
#define SMEM_BYTES (OFF_B + 4 * BSTAGE)  // 96 KB

// ---------------- device scratch ----------------
__device__ __nv_bfloat16 g_whi[NCOLS * KDIM];
__device__ __nv_bfloat16 g_wlo[NCOLS * KDIM];
__device__ float2 g_part[(size_t)NHALVES * MROWS];
__device__ int g_dummy_sink;

__device__ __forceinline__ uint32_t smem_u32(const void* p) {
    uint32_t a;
    asm("{ .reg .u64 t; cvta.to.shared.u64 t, %1; cvt.u32.u64 %0, t; }" : "=r"(a) : "l"(p));
    return a;
}

#define CP_ASYNC16(dst, src) \
    asm volatile("cp.async.cg.shared.global [%0], [%1], 16;" :: "r"(dst), "l"(src))
#define CP_COMMIT() asm volatile("cp.async.commit_group;")
#define CP_WAIT2()  asm volatile("cp.async.wait_group 2;")

__device__ __forceinline__ void ldm_x4(uint32_t addr, uint32_t& r0, uint32_t& r1,
                                       uint32_t& r2, uint32_t& r3) {
    asm volatile("ldmatrix.sync.aligned.m8n8.x4.shared.b16 {%0,%1,%2,%3}, [%4];"
                 : "=r"(r0), "=r"(r1), "=r"(r2), "=r"(r3) : "r"(addr));
}
__device__ __forceinline__ void ldm_x4t(uint32_t addr, uint32_t& r0, uint32_t& r1,
                                        uint32_t& r2, uint32_t& r3) {
    asm volatile("ldmatrix.sync.aligned.m8n8.x4.trans.shared.b16 {%0,%1,%2,%3}, [%4];"
                 : "=r"(r0), "=r"(r1), "=r"(r2), "=r"(r3) : "r"(addr));
}

__device__ __forceinline__ void mma_bf16(float& c0, float& c1, float& c2, float& c3,
                                         uint32_t a0, uint32_t a1, uint32_t a2, uint32_t a3,
                                         uint32_t b0, uint32_t b1) {
    asm volatile("mma.sync.aligned.m16n8k16.row.col.f32.bf16.bf16.f32 "
                 "{%0,%1,%2,%3}, {%4,%5,%6,%7}, {%8,%9}, {%0,%1,%2,%3};"
                 : "+f"(c0), "+f"(c1), "+f"(c2), "+f"(c3)
                 : "r"(a0), "r"(a1), "r"(a2), "r"(a3), "r"(b0), "r"(b1));
}

__device__ __forceinline__ uint32_t sw_off_b(int row, int c16) {
    return (uint32_t)(row * 64 + ((c16 ^ ((row >> 1) & 3)) << 4));
}
__device__ __forceinline__ uint32_t sw_off_a(int krow, int munit) {
    return (uint32_t)(krow * 256 + ((munit ^ (krow & 7)) << 4));
}

// ============================================================
// Dummy kernels (profiler alignment: put the GEMM at launch idx 3)
// ============================================================
__global__ void pq_dummy0_kernel() { if (threadIdx.x == 0) g_dummy_sink = 1; }
__global__ void pq_dummy1_kernel() { if (threadIdx.x == 0) g_dummy_sink = 2; }

// ============================================================
// Pre-pass: split proj_w fp32 -> bf16 hi/lo
// ============================================================
__global__ __launch_bounds__(1024)
void split_w_kernel(const float* __restrict__ w) {
    int idx = blockIdx.x * blockDim.x + threadIdx.x;
    if (idx < NCOLS * KDIM) {
        float v = w[idx];
        __nv_bfloat16 hi = __float2bfloat16(v);
        g_whi[idx] = hi;
        g_wlo[idx] = __float2bfloat16(v - __bfloat162float(hi));
    }
}

// ============================================================
// GEMM + fused logits write + perturbed partial argmax
// (round-5 structure; product order P1, P3, P2)
// ============================================================
__global__ __launch_bounds__(THREADS, 2)
void pq_gemm_kernel(const float* __restrict__ x,      // (B, Z, T)
                    const float* __restrict__ bias,
                    const float* __restrict__ gumbel,  // (BT, 640)
                    float* __restrict__ logits)
{
    extern __shared__ char smem[];
    const uint32_t sbase = smem_u32(smem);
    const int tid  = threadIdx.x;
    const int wid  = tid >> 5;
    const int lane = tid & 31;
    const int m0   = blockIdx.y * M_TILE;
    const int n0   = blockIdx.x * N_TILE;
    const int b    = m0 >> 12;
    const int t0   = m0 & 4095;

    const int mwarp = wid >> 1;
    const int nwarp = wid & 1;

    float acc[2][8][4];
#pragma unroll
    for (int mi = 0; mi < 2; mi++)
#pragma unroll
        for (int nf = 0; nf < 8; nf++)
#pragma unroll
            for (int r = 0; r < 4; r++) acc[mi][nf][r] = 0.0f;

    const float* xrow0 = x + ((size_t)b * KDIM + (size_t)(wid * 4)) * TSEQ + t0 + lane * 4;
    float4 areg[4];

    const int lrow = tid >> 1;
    const int lcb  = (tid & 1) * 2;

    auto issue_b = [&](int c) {
        const int kk = c * KC;
        const uint32_t st = sbase + OFF_B + (uint32_t)(c & 3) * BSTAGE;
#pragma unroll
        for (int u = 0; u < 2; u++) {
            int c16 = lcb + u;
            uint32_t so = sw_off_b(lrow, c16);
            const __nv_bfloat16* gh = g_whi + (size_t)(n0 + lrow) * KDIM + kk + c16 * 8;
            const __nv_bfloat16* gl = g_wlo + (size_t)(n0 + lrow) * KDIM + kk + c16 * 8;
            CP_ASYNC16(st + so, gh);
            CP_ASYNC16(st + 8192 + so, gl);
        }
        CP_COMMIT();
    };

    auto lda = [&](int c) {
#pragma unroll
        for (int i = 0; i < 4; i++)
            areg[i] = *(const float4*)(xrow0 + ((size_t)(c * KC) + i) * TSEQ);
    };

    lda(0);
    issue_b(0); issue_b(1); issue_b(2);

    for (int c = 0; c < NCHUNK; ++c) {
        {
            char* abuf = smem + OFF_ABF + (c & 1) * ABF_SLOT;
#pragma unroll
            for (int i = 0; i < 4; i++) {
                float4 v = areg[i];
                int k = wid * 4 + i;
                uint32_t off = (uint32_t)(k * 256) +
                               ((((uint32_t)(lane >> 1)) ^ (uint32_t)(k & 7)) << 4) +
                               (uint32_t)((lane & 1) * 8);
                __nv_bfloat16 h0 = __float2bfloat16(v.x);
                __nv_bfloat16 h1 = __float2bfloat16(v.y);
                __nv_bfloat16 h2 = __float2bfloat16(v.z);
                __nv_bfloat16 h3 = __float2bfloat16(v.w);
                __nv_bfloat162 hp0 = __halves2bfloat162(h0, h1);
                __nv_bfloat162 hp1 = __halves2bfloat162(h2, h3);
                ((uint2*)(abuf + off))[0] = make_uint2(*(uint32_t*)&hp0, *(uint32_t*)&hp1);
                __nv_bfloat162 lp0 = __halves2bfloat162(
                    __float2bfloat16(v.x - __bfloat162float(h0)),
                    __float2bfloat16(v.y - __bfloat162float(h1)));
                __nv_bfloat162 lp1 = __halves2bfloat162(
                    __float2bfloat16(v.z - __bfloat162float(h2)),
                    __float2bfloat16(v.w - __bfloat162float(h3)));
                ((uint2*)(abuf + 8192 + off))[0] = make_uint2(*(uint32_t*)&lp0, *(uint32_t*)&lp1);
            }
        }
        if (c + 1 < NCHUNK) lda(c + 1);

        CP_WAIT2();
        __syncthreads();
        if (c + 3 < NCHUNK) issue_b(c + 3);
        else CP_COMMIT();

        const uint32_t abase = sbase + OFF_ABF + (uint32_t)(c & 1) * ABF_SLOT;
        const uint32_t bbase = sbase + OFF_B + (uint32_t)(c & 3) * BSTAGE;

        const int grp = lane >> 3;
        const int kq  = lane & 7;

#pragma unroll
        for (int ks = 0; ks < 2; ks++) {
            const int arow = ks * 16 + ((grp >> 1) << 3) + kq;
            uint32_t ah[2][4];
#pragma unroll
            for (int mi = 0; mi < 2; mi++) {
                int munit = ((mwarp * 32 + mi * 16) >> 3) + (grp & 1);
                ldm_x4t(abase + sw_off_a(arow, munit), ah[mi][0], ah[mi][1], ah[mi][2], ah[mi][3]);
            }
            const int brow = nwarp * 64 + (lane & 7) + ((lane >> 4) << 3);
            const int bc16 = ks * 2 + ((lane >> 3) & 1);
            uint32_t bh[4][4];
#pragma unroll
            for (int j = 0; j < 4; j++)
                ldm_x4(bbase + sw_off_b(brow + j * 16, bc16), bh[j][0], bh[j][1], bh[j][2], bh[j][3]);

            // P1: Ahi x Bhi
#pragma unroll
            for (int mi = 0; mi < 2; mi++)
#pragma unroll
                for (int nf = 0; nf < 8; nf++) {
                    int j = nf >> 1, h = (nf & 1) * 2;
                    mma_bf16(acc[mi][nf][0], acc[mi][nf][1], acc[mi][nf][2], acc[mi][nf][3],
                             ah[mi][0], ah[mi][1], ah[mi][2], ah[mi][3], bh[j][h], bh[j][h + 1]);
                }

            // P3: Alo x Bhi (retires bh)
            uint32_t al[2][4];
#pragma unroll
            for (int mi = 0; mi < 2; mi++) {
                int munit = ((mwarp * 32 + mi * 16) >> 3) + (grp & 1);
                ldm_x4t(abase + 8192 + sw_off_a(arow, munit), al[mi][0], al[mi][1], al[mi][2], al[mi][3]);
            }
#pragma unroll
            for (int mi = 0; mi < 2; mi++)
#pragma unroll
                for (int nf = 0; nf < 8; nf++) {
                    int j = nf >> 1, h = (nf & 1) * 2;
                    mma_bf16(acc[mi][nf][0], acc[mi][nf][1], acc[mi][nf][2], acc[mi][nf][3],
                             al[mi][0], al[mi][1], al[mi][2], al[mi][3], bh[j][h], bh[j][h + 1]);
                }

            // P2: Ahi x Blo
            uint32_t bl[4][4];
#pragma unroll
            for (int j = 0; j < 4; j++)
                ldm_x4(bbase + 8192 + sw_off_b(brow + j * 16, bc16), bl[j][0], bl[j][1], bl[j][2], bl[j][3]);
#pragma unroll
            for (int mi = 0; mi < 2; mi++)
#pragma unroll
                for (int nf = 0; nf < 8; nf++) {
                    int j = nf >> 1, h = (nf & 1) * 2;
                    mma_bf16(acc[mi][nf][0], acc[mi][nf][1], acc[mi][nf][2], acc[mi][nf][3],
                             ah[mi][0], ah[mi][1], ah[mi][2], ah[mi][3], bl[j][h], bl[j][h + 1]);
                }
        }
    }

    // ---- fused epilogue ----
    float bestv[4];
    int   besti[4];
#pragma unroll
    for (int rp = 0; rp < 4; rp++) { bestv[rp] = -3.4e38f; besti[rp] = 0; }

#pragma unroll
    for (int nf = 0; nf < 8; nf++) {
        int col = n0 + nwarp * 64 + nf * 8 + (lane & 3) * 2;
        float b0 = __ldg(bias + col);
        float b1 = __ldg(bias + col + 1);
#pragma unroll
        for (int mi = 0; mi < 2; mi++) {
            int row = m0 + mwarp * 32 + mi * 16 + (lane >> 2);
            float v00 = acc[mi][nf][0] + b0, v01 = acc[mi][nf][1] + b1;
            float v10 = acc[mi][nf][2] + b0, v11 = acc[mi][nf][3] + b1;
            *(float2*)(logits + (size_t)row * NCOLS + col)       = make_float2(v00, v01);
            *(float2*)(logits + (size_t)(row + 8) * NCOLS + col) = make_float2(v10, v11);
            float2 g0 = *(const float2*)(gumbel + (size_t)row * NCOLS + col);
            float2 g1 = *(const float2*)(gumbel + (size_t)(row + 8) * NCOLS + col);
            float p;
            int rp0 = mi * 2, rp1 = mi * 2 + 1;
            p = v00 + g0.x; if (p > bestv[rp0]) { bestv[rp0] = p; besti[rp0] = col; }
            p = v01 + g0.y; if (p > bestv[rp0]) { bestv[rp0] = p; besti[rp0] = col + 1; }
            p = v10 + g1.x; if (p > bestv[rp1]) { bestv[rp1] = p; besti[rp1] = col; }
            p = v11 + g1.y; if (p > bestv[rp1]) { bestv[rp1] = p; besti[rp1] = col + 1; }
        }
    }

#pragma unroll
    for (int rp = 0; rp < 4; rp++) {
#pragma unroll
        for (int off = 1; off <= 2; off <<= 1) {
            float ov = __shfl_xor_sync(0xffffffffu, bestv[rp], off);
            int   oi = __shfl_xor_sync(0xffffffffu, besti[rp], off);
            if (ov > bestv[rp] || (ov == bestv[rp] && oi < besti[rp])) {
                bestv[rp] = ov; besti[rp] = oi;
            }
        }
    }
    if ((lane & 3) == 0) {
        const int h = blockIdx.x * 2 + nwarp;
#pragma unroll
        for (int rp = 0; rp < 4; rp++) {
            int row = m0 + mwarp * 32 + (rp >> 1) * 16 + (rp & 1) * 8 + (lane >> 2);
            g_part[(size_t)h * MROWS + row] = make_float2(bestv[rp], __int_as_float(besti[rp]));
        }
    }
}

// ============================================================
// Combine: winner among 5 halves per group, gather codevector
// ============================================================
__global__ __launch_bounds__(256)
void pq_combine_kernel(const float* __restrict__ cv,
                       float* __restrict__ q)
{
    const int warp = (blockIdx.x * blockDim.x + threadIdx.x) >> 5;
    const int lane = threadIdx.x & 31;
    if (warp >= MROWS * NGROUPS) return;

    const int bt = warp >> 1;
    const int g  = warp & 1;

    float best = -3.4e38f;
    int   bcol = 0;
#pragma unroll
    for (int j = 0; j < 5; j++) {
        float2 p = g_part[(size_t)(g * 5 + j) * MROWS + bt];
        if (p.x > best) { best = p.x; bcol = __float_as_int(p.y); }
    }

    const float4* src = (const float4*)(cv + (size_t)bcol * VDIM);
    float4*       dst = (float4*)(q + (size_t)bt * (NGROUPS * VDIM) + g * VDIM);
    dst[lane] = src[lane];
}

// ============================================================
extern "C" void kernel_launch(void* const* d_in, const int* in_sizes, int n_in,
                              void* d_out, int out_size) {
    const float* x      = (const float*)d_in[0];
    const float* gumbel = (const float*)d_in[1];
    const float* proj_w = (const float*)d_in[2];
    const float* proj_b = (const float*)d_in[3];
    const float* cv     = (const float*)d_in[4];

    float* out    = (float*)d_out;
    float* logits = out;
    float* q      = out + LOGITS_ELEMS;

    // dummies shift the GEMM to launch index 3 so ncu profiles it
    pq_dummy0_kernel<<<1, 32>>>();
    pq_dummy1_kernel<<<1, 32>>>();

    split_w_kernel<<<(NCOLS * KDIM + 1023) / 1024, 1024>>>(proj_w);

    cudaFuncSetAttribute(pq_gemm_kernel,
                         cudaFuncAttributeMaxDynamicSharedMemorySize, SMEM_BYTES);
    pq_gemm_kernel<<<dim3(NCOLS / N_TILE, MROWS / M_TILE), THREADS, SMEM_BYTES>>>(
        x, proj_b, gumbel, logits);

    int blocks = (MROWS * NGROUPS * 32 + 255) / 256;
    pq_combine_kernel<<<blocks, 256>>>(cv, q);
}

// round 8
// speedup vs baseline: 1.1358x; 1.0951x over previous
#include <cuda_runtime.h>
#include <cuda_bf16.h>
#include <cstdint>

// ---------------- problem constants ----------------
#define BATCH    16
#define ZDIM     512
#define TSEQ     4096
#define NGROUPS  2
#define NENTRIES 320
#define VDIM     128
#define MROWS    (BATCH * TSEQ)          // 65536
#define NCOLS    (NGROUPS * NENTRIES)    // 640
#define KDIM     ZDIM                    // 512
#define LOGITS_ELEMS ((size_t)MROWS * NCOLS)

// ---------------- GEMM tiling ----------------
#define M_TILE   128
#define N_TILE   128
#define KC       32
#define NCHUNK   (KDIM / KC)             // 16
#define THREADS  256
#define NHALVES  10

#define ABF_SLOT   16384
#define OFF_ABF    0
#define OFF_B      32768
#define BSTAGE     16384
#define SMEM_BYTES (OFF_B + 4 * BSTAGE)  // 96 KB

// ---------------- device scratch ----------------
__device__ __nv_bfloat16 g_whi[NCOLS * KDIM];
__device__ __nv_bfloat16 g_wlo[NCOLS * KDIM];
__device__ float2 g_part[(size_t)NHALVES * MROWS];

__device__ __forceinline__ uint32_t smem_u32(const void* p) {
    uint32_t a;
    asm("{ .reg .u64 t; cvta.to.shared.u64 t, %1; cvt.u32.u64 %0, t; }" : "=r"(a) : "l"(p));
    return a;
}

#define CP_ASYNC16(dst, src) \
    asm volatile("cp.async.cg.shared.global [%0], [%1], 16;" :: "r"(dst), "l"(src))
#define CP_COMMIT() asm volatile("cp.async.commit_group;")
#define CP_WAIT2()  asm volatile("cp.async.wait_group 2;")

__device__ __forceinline__ void ldm_x4(uint32_t addr, uint32_t& r0, uint32_t& r1,
                                       uint32_t& r2, uint32_t& r3) {
    asm volatile("ldmatrix.sync.aligned.m8n8.x4.shared.b16 {%0,%1,%2,%3}, [%4];"
                 : "=r"(r0), "=r"(r1), "=r"(r2), "=r"(r3) : "r"(addr));
}
__device__ __forceinline__ void ldm_x4t(uint32_t addr, uint32_t& r0, uint32_t& r1,
                                        uint32_t& r2, uint32_t& r3) {
    asm volatile("ldmatrix.sync.aligned.m8n8.x4.trans.shared.b16 {%0,%1,%2,%3}, [%4];"
                 : "=r"(r0), "=r"(r1), "=r"(r2), "=r"(r3) : "r"(addr));
}

__device__ __forceinline__ void mma_bf16(float& c0, float& c1, float& c2, float& c3,
                                         uint32_t a0, uint32_t a1, uint32_t a2, uint32_t a3,
                                         uint32_t b0, uint32_t b1) {
    asm volatile("mma.sync.aligned.m16n8k16.row.col.f32.bf16.bf16.f32 "
                 "{%0,%1,%2,%3}, {%4,%5,%6,%7}, {%8,%9}, {%0,%1,%2,%3};"
                 : "+f"(c0), "+f"(c1), "+f"(c2), "+f"(c3)
                 : "r"(a0), "r"(a1), "r"(a2), "r"(a3), "r"(b0), "r"(b1));
}

__device__ __forceinline__ uint32_t sw_off_b(int row, int c16) {
    return (uint32_t)(row * 64 + ((c16 ^ ((row >> 1) & 3)) << 4));
}
__device__ __forceinline__ uint32_t sw_off_a(int krow, int munit) {
    return (uint32_t)(krow * 256 + ((munit ^ (krow & 7)) << 4));
}

// ============================================================
// Pre-pass: split proj_w fp32 -> bf16 hi/lo
// ============================================================
__global__ __launch_bounds__(1024)
void split_w_kernel(const float* __restrict__ w) {
    int idx = blockIdx.x * blockDim.x + threadIdx.x;
    if (idx < NCOLS * KDIM) {
        float v = w[idx];
        __nv_bfloat16 hi = __float2bfloat16(v);
        g_whi[idx] = hi;
        g_wlo[idx] = __float2bfloat16(v - __bfloat162float(hi));
    }
}

// ============================================================
// GEMM + fused logits write + perturbed partial argmax.
// Inner loop: B(hi+lo) loads grouped up-front; per-mi A loads then
// 24 back-to-back mmas so LDSM latency hides under the mma stream.
// ============================================================
__global__ __launch_bounds__(THREADS, 2)
void pq_gemm_kernel(const float* __restrict__ x,      // (B, Z, T)
                    const float* __restrict__ bias,
                    const float* __restrict__ gumbel,  // (BT, 640)
                    float* __restrict__ logits)
{
    extern __shared__ char smem[];
    const uint32_t sbase = smem_u32(smem);
    const int tid  = threadIdx.x;
    const int wid  = tid >> 5;
    const int lane = tid & 31;
    const int m0   = blockIdx.y * M_TILE;
    const int n0   = blockIdx.x * N_TILE;
    const int b    = m0 >> 12;
    const int t0   = m0 & 4095;

    const int mwarp = wid >> 1;
    const int nwarp = wid & 1;

    float acc[2][8][4];
#pragma unroll
    for (int mi = 0; mi < 2; mi++)
#pragma unroll
        for (int nf = 0; nf < 8; nf++)
#pragma unroll
            for (int r = 0; r < 4; r++) acc[mi][nf][r] = 0.0f;

    const float* xrow0 = x + ((size_t)b * KDIM + (size_t)(wid * 4)) * TSEQ + t0 + lane * 4;
    float4 areg[4];

    const int lrow = tid >> 1;
    const int lcb  = (tid & 1) * 2;

    auto issue_b = [&](int c) {
        const int kk = c * KC;
        const uint32_t st = sbase + OFF_B + (uint32_t)(c & 3) * BSTAGE;
#pragma unroll
        for (int u = 0; u < 2; u++) {
            int c16 = lcb + u;
            uint32_t so = sw_off_b(lrow, c16);
            const __nv_bfloat16* gh = g_whi + (size_t)(n0 + lrow) * KDIM + kk + c16 * 8;
            const __nv_bfloat16* gl = g_wlo + (size_t)(n0 + lrow) * KDIM + kk + c16 * 8;
            CP_ASYNC16(st + so, gh);
            CP_ASYNC16(st + 8192 + so, gl);
        }
        CP_COMMIT();
    };

    auto lda = [&](int c) {
#pragma unroll
        for (int i = 0; i < 4; i++)
            areg[i] = *(const float4*)(xrow0 + ((size_t)(c * KC) + i) * TSEQ);
    };

    lda(0);
    issue_b(0); issue_b(1); issue_b(2);

    for (int c = 0; c < NCHUNK; ++c) {
        // ---- convert A regs -> bf16 hi/lo smem (overlaps cp.async wait) ----
        {
            char* abuf = smem + OFF_ABF + (c & 1) * ABF_SLOT;
#pragma unroll
            for (int i = 0; i < 4; i++) {
                float4 v = areg[i];
                int k = wid * 4 + i;
                uint32_t off = (uint32_t)(k * 256) +
                               ((((uint32_t)(lane >> 1)) ^ (uint32_t)(k & 7)) << 4) +
                               (uint32_t)((lane & 1) * 8);
                __nv_bfloat16 h0 = __float2bfloat16(v.x);
                __nv_bfloat16 h1 = __float2bfloat16(v.y);
                __nv_bfloat16 h2 = __float2bfloat16(v.z);
                __nv_bfloat16 h3 = __float2bfloat16(v.w);
                __nv_bfloat162 hp0 = __halves2bfloat162(h0, h1);
                __nv_bfloat162 hp1 = __halves2bfloat162(h2, h3);
                ((uint2*)(abuf + off))[0] = make_uint2(*(uint32_t*)&hp0, *(uint32_t*)&hp1);
                __nv_bfloat162 lp0 = __halves2bfloat162(
                    __float2bfloat16(v.x - __bfloat162float(h0)),
                    __float2bfloat16(v.y - __bfloat162float(h1)));
                __nv_bfloat162 lp1 = __halves2bfloat162(
                    __float2bfloat16(v.z - __bfloat162float(h2)),
                    __float2bfloat16(v.w - __bfloat162float(h3)));
                ((uint2*)(abuf + 8192 + off))[0] = make_uint2(*(uint32_t*)&lp0, *(uint32_t*)&lp1);
            }
        }
        if (c + 1 < NCHUNK) lda(c + 1);

        CP_WAIT2();
        __syncthreads();
        if (c + 3 < NCHUNK) issue_b(c + 3);
        else CP_COMMIT();

        const uint32_t abase = sbase + OFF_ABF + (uint32_t)(c & 1) * ABF_SLOT;
        const uint32_t bbase = sbase + OFF_B + (uint32_t)(c & 3) * BSTAGE;

        const int grp = lane >> 3;
        const int kq  = lane & 7;
        const int brow = nwarp * 64 + (lane & 7) + ((lane >> 4) << 3);

#pragma unroll
        for (int ks = 0; ks < 2; ks++) {
            const int arow = ks * 16 + ((grp >> 1) << 3) + kq;
            const int bc16 = ks * 2 + ((lane >> 3) & 1);

            // ---- all B fragments (hi + lo) loaded up-front ----
            uint32_t bh[4][4], bl[4][4];
#pragma unroll
            for (int j = 0; j < 4; j++)
                ldm_x4(bbase + sw_off_b(brow + j * 16, bc16), bh[j][0], bh[j][1], bh[j][2], bh[j][3]);
#pragma unroll
            for (int j = 0; j < 4; j++)
                ldm_x4(bbase + 8192 + sw_off_b(brow + j * 16, bc16), bl[j][0], bl[j][1], bl[j][2], bl[j][3]);

            // ---- per-mi: load A hi+lo, then 24 dependent mmas ----
#pragma unroll
            for (int mi = 0; mi < 2; mi++) {
                int munit = ((mwarp * 32 + mi * 16) >> 3) + (grp & 1);
                uint32_t ah[4], al[4];
                ldm_x4t(abase + sw_off_a(arow, munit), ah[0], ah[1], ah[2], ah[3]);
                ldm_x4t(abase + 8192 + sw_off_a(arow, munit), al[0], al[1], al[2], al[3]);

                // P1: Ahi x Bhi
#pragma unroll
                for (int nf = 0; nf < 8; nf++) {
                    int j = nf >> 1, h = (nf & 1) * 2;
                    mma_bf16(acc[mi][nf][0], acc[mi][nf][1], acc[mi][nf][2], acc[mi][nf][3],
                             ah[0], ah[1], ah[2], ah[3], bh[j][h], bh[j][h + 1]);
                }
                // P2: Ahi x Blo
#pragma unroll
                for (int nf = 0; nf < 8; nf++) {
                    int j = nf >> 1, h = (nf & 1) * 2;
                    mma_bf16(acc[mi][nf][0], acc[mi][nf][1], acc[mi][nf][2], acc[mi][nf][3],
                             ah[0], ah[1], ah[2], ah[3], bl[j][h], bl[j][h + 1]);
                }
                // P3: Alo x Bhi
#pragma unroll
                for (int nf = 0; nf < 8; nf++) {
                    int j = nf >> 1, h = (nf & 1) * 2;
                    mma_bf16(acc[mi][nf][0], acc[mi][nf][1], acc[mi][nf][2], acc[mi][nf][3],
                             al[0], al[1], al[2], al[3], bh[j][h], bh[j][h + 1]);
                }
            }
        }
    }

    // ---- fused epilogue ----
    float bestv[4];
    int   besti[4];
#pragma unroll
    for (int rp = 0; rp < 4; rp++) { bestv[rp] = -3.4e38f; besti[rp] = 0; }

#pragma unroll
    for (int nf = 0; nf < 8; nf++) {
        int col = n0 + nwarp * 64 + nf * 8 + (lane & 3) * 2;
        float b0 = __ldg(bias + col);
        float b1 = __ldg(bias + col + 1);
#pragma unroll
        for (int mi = 0; mi < 2; mi++) {
            int row = m0 + mwarp * 32 + mi * 16 + (lane >> 2);
            float v00 = acc[mi][nf][0] + b0, v01 = acc[mi][nf][1] + b1;
            float v10 = acc[mi][nf][2] + b0, v11 = acc[mi][nf][3] + b1;
            *(float2*)(logits + (size_t)row * NCOLS + col)       = make_float2(v00, v01);
            *(float2*)(logits + (size_t)(row + 8) * NCOLS + col) = make_float2(v10, v11);
            float2 g0 = *(const float2*)(gumbel + (size_t)row * NCOLS + col);
            float2 g1 = *(const float2*)(gumbel + (size_t)(row + 8) * NCOLS + col);
            float p;
            int rp0 = mi * 2, rp1 = mi * 2 + 1;
            p = v00 + g0.x; if (p > bestv[rp0]) { bestv[rp0] = p; besti[rp0] = col; }
            p = v01 + g0.y; if (p > bestv[rp0]) { bestv[rp0] = p; besti[rp0] = col + 1; }
            p = v10 + g1.x; if (p > bestv[rp1]) { bestv[rp1] = p; besti[rp1] = col; }
            p = v11 + g1.y; if (p > bestv[rp1]) { bestv[rp1] = p; besti[rp1] = col + 1; }
        }
    }

#pragma unroll
    for (int rp = 0; rp < 4; rp++) {
#pragma unroll
        for (int off = 1; off <= 2; off <<= 1) {
            float ov = __shfl_xor_sync(0xffffffffu, bestv[rp], off);
            int   oi = __shfl_xor_sync(0xffffffffu, besti[rp], off);
            if (ov > bestv[rp] || (ov == bestv[rp] && oi < besti[rp])) {
                bestv[rp] = ov; besti[rp] = oi;
            }
        }
    }
    if ((lane & 3) == 0) {
        const int h = blockIdx.x * 2 + nwarp;
#pragma unroll
        for (int rp = 0; rp < 4; rp++) {
            int row = m0 + mwarp * 32 + (rp >> 1) * 16 + (rp & 1) * 8 + (lane >> 2);
            g_part[(size_t)h * MROWS + row] = make_float2(bestv[rp], __int_as_float(besti[rp]));
        }
    }
}

// ============================================================
// Combine: winner among 5 halves per group, gather codevector
// ============================================================
__global__ __launch_bounds__(256)
void pq_combine_kernel(const float* __restrict__ cv,
                       float* __restrict__ q)
{
    const int warp = (blockIdx.x * blockDim.x + threadIdx.x) >> 5;
    const int lane = threadIdx.x & 31;
    if (warp >= MROWS * NGROUPS) return;

    const int bt = warp >> 1;
    const int g  = warp & 1;

    float best = -3.4e38f;
    int   bcol = 0;
#pragma unroll
    for (int j = 0; j < 5; j++) {
        float2 p = g_part[(size_t)(g * 5 + j) * MROWS + bt];
        if (p.x > best) { best = p.x; bcol = __float_as_int(p.y); }
    }

    const float4* src = (const float4*)(cv + (size_t)bcol * VDIM);
    float4*       dst = (float4*)(q + (size_t)bt * (NGROUPS * VDIM) + g * VDIM);
    dst[lane] = src[lane];
}

// ============================================================
extern "C" void kernel_launch(void* const* d_in, const int* in_sizes, int n_in,
                              void* d_out, int out_size) {
    const float* x      = (const float*)d_in[0];
    const float* gumbel = (const float*)d_in[1];
    const float* proj_w = (const float*)d_in[2];
    const float* proj_b = (const float*)d_in[3];
    const float* cv     = (const float*)d_in[4];

    float* out    = (float*)d_out;
    float* logits = out;
    float* q      = out + LOGITS_ELEMS;

    split_w_kernel<<<(NCOLS * KDIM + 1023) / 1024, 1024>>>(proj_w);

    cudaFuncSetAttribute(pq_gemm_kernel,
                         cudaFuncAttributeMaxDynamicSharedMemorySize, SMEM_BYTES);
    pq_gemm_kernel<<<dim3(NCOLS / N_TILE, MROWS / M_TILE), THREADS, SMEM_BYTES>>>(
        x, proj_b, gumbel, logits);

    int blocks = (MROWS * NGROUPS * 32 + 255) / 256;
    pq_combine_kernel<<<blocks, 256>>>(cv, q);
}

// round 9
// speedup vs baseline: 1.1729x; 1.0327x over previous
#include <cuda_runtime.h>
#include <cuda_bf16.h>
#include <cstdint>

// ---------------- problem constants ----------------
#define BATCH    16
#define ZDIM     512
#define TSEQ     4096
#define NGROUPS  2
#define NENTRIES 320
#define VDIM     128
#define MROWS    (BATCH * TSEQ)          // 65536
#define NCOLS    (NGROUPS * NENTRIES)    // 640
#define KDIM     ZDIM                    // 512
#define LOGITS_ELEMS ((size_t)MROWS * NCOLS)

// ---------------- GEMM tiling ----------------
#define M_TILE   128
#define N_TILE   128
#define KC       32
#define NCHUNK   (KDIM / KC)             // 16
#define THREADS  256
#define NHALVES  10

#define ABF_SLOT   16384
#define OFF_ABF    0
#define OFF_B      32768
#define BSTAGE     16384
#define SMEM_BYTES (OFF_B + 4 * BSTAGE)  // 96 KB

// ---------------- device scratch ----------------
__device__ __nv_bfloat16 g_whi[NCOLS * KDIM];
__device__ __nv_bfloat16 g_wlo[NCOLS * KDIM];
__device__ float2 g_part[(size_t)NHALVES * MROWS];

__device__ __forceinline__ uint32_t smem_u32(const void* p) {
    uint32_t a;
    asm("{ .reg .u64 t; cvta.to.shared.u64 t, %1; cvt.u32.u64 %0, t; }" : "=r"(a) : "l"(p));
    return a;
}

#define CP_ASYNC16(dst, src) \
    asm volatile("cp.async.cg.shared.global [%0], [%1], 16;" :: "r"(dst), "l"(src))
#define CP_COMMIT() asm volatile("cp.async.commit_group;")
#define CP_WAIT2()  asm volatile("cp.async.wait_group 2;")

__device__ __forceinline__ void ldm_x4(uint32_t addr, uint32_t& r0, uint32_t& r1,
                                       uint32_t& r2, uint32_t& r3) {
    asm volatile("ldmatrix.sync.aligned.m8n8.x4.shared.b16 {%0,%1,%2,%3}, [%4];"
                 : "=r"(r0), "=r"(r1), "=r"(r2), "=r"(r3) : "r"(addr));
}
__device__ __forceinline__ void ldm_x4t(uint32_t addr, uint32_t& r0, uint32_t& r1,
                                        uint32_t& r2, uint32_t& r3) {
    asm volatile("ldmatrix.sync.aligned.m8n8.x4.trans.shared.b16 {%0,%1,%2,%3}, [%4];"
                 : "=r"(r0), "=r"(r1), "=r"(r2), "=r"(r3) : "r"(addr));
}

__device__ __forceinline__ void mma_bf16(float& c0, float& c1, float& c2, float& c3,
                                         uint32_t a0, uint32_t a1, uint32_t a2, uint32_t a3,
                                         uint32_t b0, uint32_t b1) {
    asm volatile("mma.sync.aligned.m16n8k16.row.col.f32.bf16.bf16.f32 "
                 "{%0,%1,%2,%3}, {%4,%5,%6,%7}, {%8,%9}, {%0,%1,%2,%3};"
                 : "+f"(c0), "+f"(c1), "+f"(c2), "+f"(c3)
                 : "r"(a0), "r"(a1), "r"(a2), "r"(a3), "r"(b0), "r"(b1));
}

__device__ __forceinline__ uint32_t sw_off_b(int row, int c16) {
    return (uint32_t)(row * 64 + ((c16 ^ ((row >> 1) & 3)) << 4));
}
__device__ __forceinline__ uint32_t sw_off_a(int krow, int munit) {
    return (uint32_t)(krow * 256 + ((munit ^ (krow & 7)) << 4));
}

// ============================================================
// Pre-pass: split proj_w fp32 -> bf16 hi/lo
// ============================================================
__global__ __launch_bounds__(1024)
void split_w_kernel(const float* __restrict__ w) {
    int idx = blockIdx.x * blockDim.x + threadIdx.x;
    if (idx < NCOLS * KDIM) {
        float v = w[idx];
        __nv_bfloat16 hi = __float2bfloat16(v);
        g_whi[idx] = hi;
        g_wlo[idx] = __float2bfloat16(v - __bfloat162float(hi));
    }
}

// ============================================================
// GEMM + fused logits write + perturbed partial argmax.
// Inner loop: A hi/lo loaded once per k16 (reused by 48 mmas);
// B loaded per-j (8 regs live) -> low peak liveness so ptxas can
// software-pipeline LDSM under the mma stream within 128 regs.
// ============================================================
__global__ __launch_bounds__(THREADS, 2)
void pq_gemm_kernel(const float* __restrict__ x,      // (B, Z, T)
                    const float* __restrict__ bias,
                    const float* __restrict__ gumbel,  // (BT, 640)
                    float* __restrict__ logits)
{
    extern __shared__ char smem[];
    const uint32_t sbase = smem_u32(smem);
    const int tid  = threadIdx.x;
    const int wid  = tid >> 5;
    const int lane = tid & 31;
    const int m0   = blockIdx.y * M_TILE;
    const int n0   = blockIdx.x * N_TILE;
    const int b    = m0 >> 12;
    const int t0   = m0 & 4095;

    const int mwarp = wid >> 1;
    const int nwarp = wid & 1;

    float acc[2][8][4];
#pragma unroll
    for (int mi = 0; mi < 2; mi++)
#pragma unroll
        for (int nf = 0; nf < 8; nf++)
#pragma unroll
            for (int r = 0; r < 4; r++) acc[mi][nf][r] = 0.0f;

    const float* xrow0 = x + ((size_t)b * KDIM + (size_t)(wid * 4)) * TSEQ + t0 + lane * 4;
    float4 areg[4];

    const int lrow = tid >> 1;
    const int lcb  = (tid & 1) * 2;

    auto issue_b = [&](int c) {
        const int kk = c * KC;
        const uint32_t st = sbase + OFF_B + (uint32_t)(c & 3) * BSTAGE;
#pragma unroll
        for (int u = 0; u < 2; u++) {
            int c16 = lcb + u;
            uint32_t so = sw_off_b(lrow, c16);
            const __nv_bfloat16* gh = g_whi + (size_t)(n0 + lrow) * KDIM + kk + c16 * 8;
            const __nv_bfloat16* gl = g_wlo + (size_t)(n0 + lrow) * KDIM + kk + c16 * 8;
            CP_ASYNC16(st + so, gh);
            CP_ASYNC16(st + 8192 + so, gl);
        }
        CP_COMMIT();
    };

    auto lda = [&](int c) {
#pragma unroll
        for (int i = 0; i < 4; i++)
            areg[i] = *(const float4*)(xrow0 + ((size_t)(c * KC) + i) * TSEQ);
    };

    lda(0);
    issue_b(0); issue_b(1); issue_b(2);

    for (int c = 0; c < NCHUNK; ++c) {
        // ---- convert A regs -> bf16 hi/lo smem (overlaps cp.async wait) ----
        {
            char* abuf = smem + OFF_ABF + (c & 1) * ABF_SLOT;
#pragma unroll
            for (int i = 0; i < 4; i++) {
                float4 v = areg[i];
                int k = wid * 4 + i;
                uint32_t off = (uint32_t)(k * 256) +
                               ((((uint32_t)(lane >> 1)) ^ (uint32_t)(k & 7)) << 4) +
                               (uint32_t)((lane & 1) * 8);
                __nv_bfloat16 h0 = __float2bfloat16(v.x);
                __nv_bfloat16 h1 = __float2bfloat16(v.y);
                __nv_bfloat16 h2 = __float2bfloat16(v.z);
                __nv_bfloat16 h3 = __float2bfloat16(v.w);
                __nv_bfloat162 hp0 = __halves2bfloat162(h0, h1);
                __nv_bfloat162 hp1 = __halves2bfloat162(h2, h3);
                ((uint2*)(abuf + off))[0] = make_uint2(*(uint32_t*)&hp0, *(uint32_t*)&hp1);
                __nv_bfloat162 lp0 = __halves2bfloat162(
                    __float2bfloat16(v.x - __bfloat162float(h0)),
                    __float2bfloat16(v.y - __bfloat162float(h1)));
                __nv_bfloat162 lp1 = __halves2bfloat162(
                    __float2bfloat16(v.z - __bfloat162float(h2)),
                    __float2bfloat16(v.w - __bfloat162float(h3)));
                ((uint2*)(abuf + 8192 + off))[0] = make_uint2(*(uint32_t*)&lp0, *(uint32_t*)&lp1);
            }
        }
        if (c + 1 < NCHUNK) lda(c + 1);

        CP_WAIT2();
        __syncthreads();
        if (c + 3 < NCHUNK) issue_b(c + 3);
        else CP_COMMIT();

        const uint32_t abase = sbase + OFF_ABF + (uint32_t)(c & 1) * ABF_SLOT;
        const uint32_t bbase = sbase + OFF_B + (uint32_t)(c & 3) * BSTAGE;

        const int grp = lane >> 3;
        const int kq  = lane & 7;
        const int brow = nwarp * 64 + (lane & 7) + ((lane >> 4) << 3);

#pragma unroll
        for (int ks = 0; ks < 2; ks++) {
            const int arow = ks * 16 + ((grp >> 1) << 3) + kq;
            const int bc16 = ks * 2 + ((lane >> 3) & 1);

            // ---- A hi+lo for both mi, loaded once per k16 (32 regs) ----
            uint32_t ah[2][4], al[2][4];
#pragma unroll
            for (int mi = 0; mi < 2; mi++) {
                int munit = ((mwarp * 32 + mi * 16) >> 3) + (grp & 1);
                ldm_x4t(abase + sw_off_a(arow, munit), ah[mi][0], ah[mi][1], ah[mi][2], ah[mi][3]);
                ldm_x4t(abase + 8192 + sw_off_a(arow, munit), al[mi][0], al[mi][1], al[mi][2], al[mi][3]);
            }

            // ---- per-j: load only bh[j]+bl[j] (8 regs), 12 mmas ----
#pragma unroll
            for (int j = 0; j < 4; j++) {
                uint32_t bh[4], bl[4];
                ldm_x4(bbase + sw_off_b(brow + j * 16, bc16), bh[0], bh[1], bh[2], bh[3]);
                ldm_x4(bbase + 8192 + sw_off_b(brow + j * 16, bc16), bl[0], bl[1], bl[2], bl[3]);
#pragma unroll
                for (int mi = 0; mi < 2; mi++) {
#pragma unroll
                    for (int t = 0; t < 2; t++) {
                        int nf = j * 2 + t;
                        int h  = t * 2;
                        // P1: Ahi x Bhi
                        mma_bf16(acc[mi][nf][0], acc[mi][nf][1], acc[mi][nf][2], acc[mi][nf][3],
                                 ah[mi][0], ah[mi][1], ah[mi][2], ah[mi][3], bh[h], bh[h + 1]);
                        // P2: Ahi x Blo
                        mma_bf16(acc[mi][nf][0], acc[mi][nf][1], acc[mi][nf][2], acc[mi][nf][3],
                                 ah[mi][0], ah[mi][1], ah[mi][2], ah[mi][3], bl[h], bl[h + 1]);
                        // P3: Alo x Bhi
                        mma_bf16(acc[mi][nf][0], acc[mi][nf][1], acc[mi][nf][2], acc[mi][nf][3],
                                 al[mi][0], al[mi][1], al[mi][2], al[mi][3], bh[h], bh[h + 1]);
                    }
                }
            }
        }
    }

    // ---- fused epilogue ----
    float bestv[4];
    int   besti[4];
#pragma unroll
    for (int rp = 0; rp < 4; rp++) { bestv[rp] = -3.4e38f; besti[rp] = 0; }

#pragma unroll
    for (int nf = 0; nf < 8; nf++) {
        int col = n0 + nwarp * 64 + nf * 8 + (lane & 3) * 2;
        float b0 = __ldg(bias + col);
        float b1 = __ldg(bias + col + 1);
#pragma unroll
        for (int mi = 0; mi < 2; mi++) {
            int row = m0 + mwarp * 32 + mi * 16 + (lane >> 2);
            float v00 = acc[mi][nf][0] + b0, v01 = acc[mi][nf][1] + b1;
            float v10 = acc[mi][nf][2] + b0, v11 = acc[mi][nf][3] + b1;
            *(float2*)(logits + (size_t)row * NCOLS + col)       = make_float2(v00, v01);
            *(float2*)(logits + (size_t)(row + 8) * NCOLS + col) = make_float2(v10, v11);
            float2 g0 = *(const float2*)(gumbel + (size_t)row * NCOLS + col);
            float2 g1 = *(const float2*)(gumbel + (size_t)(row + 8) * NCOLS + col);
            float p;
            int rp0 = mi * 2, rp1 = mi * 2 + 1;
            p = v00 + g0.x; if (p > bestv[rp0]) { bestv[rp0] = p; besti[rp0] = col; }
            p = v01 + g0.y; if (p > bestv[rp0]) { bestv[rp0] = p; besti[rp0] = col + 1; }
            p = v10 + g1.x; if (p > bestv[rp1]) { bestv[rp1] = p; besti[rp1] = col; }
            p = v11 + g1.y; if (p > bestv[rp1]) { bestv[rp1] = p; besti[rp1] = col + 1; }
        }
    }

#pragma unroll
    for (int rp = 0; rp < 4; rp++) {
#pragma unroll
        for (int off = 1; off <= 2; off <<= 1) {
            float ov = __shfl_xor_sync(0xffffffffu, bestv[rp], off);
            int   oi = __shfl_xor_sync(0xffffffffu, besti[rp], off);
            if (ov > bestv[rp] || (ov == bestv[rp] && oi < besti[rp])) {
                bestv[rp] = ov; besti[rp] = oi;
            }
        }
    }
    if ((lane & 3) == 0) {
        const int h = blockIdx.x * 2 + nwarp;
#pragma unroll
        for (int rp = 0; rp < 4; rp++) {
            int row = m0 + mwarp * 32 + (rp >> 1) * 16 + (rp & 1) * 8 + (lane >> 2);
            g_part[(size_t)h * MROWS + row] = make_float2(bestv[rp], __int_as_float(besti[rp]));
        }
    }
}

// ============================================================
// Combine: winner among 5 halves per group, gather codevector
// ============================================================
__global__ __launch_bounds__(256)
void pq_combine_kernel(const float* __restrict__ cv,
                       float* __restrict__ q)
{
    const int warp = (blockIdx.x * blockDim.x + threadIdx.x) >> 5;
    const int lane = threadIdx.x & 31;
    if (warp >= MROWS * NGROUPS) return;

    const int bt = warp >> 1;
    const int g  = warp & 1;

    float best = -3.4e38f;
    int   bcol = 0;
#pragma unroll
    for (int j = 0; j < 5; j++) {
        float2 p = g_part[(size_t)(g * 5 + j) * MROWS + bt];
        if (p.x > best) { best = p.x; bcol = __float_as_int(p.y); }
    }

    const float4* src = (const float4*)(cv + (size_t)bcol * VDIM);
    float4*       dst = (float4*)(q + (size_t)bt * (NGROUPS * VDIM) + g * VDIM);
    dst[lane] = src[lane];
}

// ============================================================
extern "C" void kernel_launch(void* const* d_in, const int* in_sizes, int n_in,
                              void* d_out, int out_size) {
    const float* x      = (const float*)d_in[0];
    const float* gumbel = (const float*)d_in[1];
    const float* proj_w = (const float*)d_in[2];
    const float* proj_b = (const float*)d_in[3];
    const float* cv     = (const float*)d_in[4];

    float* out    = (float*)d_out;
    float* logits = out;
    float* q      = out + LOGITS_ELEMS;

    split_w_kernel<<<(NCOLS * KDIM + 1023) / 1024, 1024>>>(proj_w);

    cudaFuncSetAttribute(pq_gemm_kernel,
                         cudaFuncAttributeMaxDynamicSharedMemorySize, SMEM_BYTES);
    pq_gemm_kernel<<<dim3(NCOLS / N_TILE, MROWS / M_TILE), THREADS, SMEM_BYTES>>>(
        x, proj_b, gumbel, logits);

    int blocks = (MROWS * NGROUPS * 32 + 255) / 256;
    pq_combine_kernel<<<blocks, 256>>>(cv, q);
}